// round 9
// baseline (speedup 1.0000x reference)
#include <cuda_runtime.h>
#include <cstdint>
#include <math.h>

// ---------------- problem constants ----------------
#define NF     128
#define BATCH  4
#define TT     8
#define NPIX   1024
#define CIN1   384
#define CIN23  256
#define K1     (CIN1 * 9)     // 3456
#define K23    (CIN23 * 9)    // 2304
#define NCH1   108            // K1/32
#define NCH23  72             // K23/32
#define PADPL  (34 * 36)      // padded plane (34 rows x 36 cols)

// pad buffer strides (floats)
#define XC   (BATCH * 256 * PADPL)
#define H1C  (BATCH * 128 * PADPL)
#define H1P  (3 * H1C)
#define L2C  (BATCH * 256 * PADPL)
#define L2P  (3 * L2C)

// GEMM tiling: CTA 64x64x32, 8 warps (2m x 4n), warp tile 32x16, mma m16n8k8
#define BM 64
#define STAGES 4
#define A_ST 2304              // 32 k-rows * 72 (72 mod 32 == 8: bank-bijective)
#define B_ST 2048              // 64 n * 32 k
#define STG  (A_ST + B_ST)     // 4352 floats per stage
#define SMEM_DYN (STAGES * STG * 4)   // 69632 B -> 3 CTAs/SM

// ---------------- persistent device scratch ----------------
__device__ __align__(256) float g_padX[3 * XC];
__device__ __align__(256) float g_padH1[2 * H1P];
__device__ __align__(256) float g_padL2[2 * L2P];
__device__ __align__(256) float g_padL3[2 * L2P];
__device__ __align__(256) float g_c1[BATCH * NF * NPIX];
__device__ __align__(256) float g_c2[BATCH * NF * NPIX];
__device__ __align__(256) float g_c3[BATCH * NF * NPIX];
__device__ __align__(256) float g_wf1[K1 * 512];
__device__ __align__(256) float g_wf2[K23 * 512];
__device__ __align__(256) float g_wf3[K23 * 512];
__device__ float g_bp1[512];
__device__ float g_bp2[512];
__device__ float g_bp3[512];

__device__ __forceinline__ float f2tf32(float x) {
    uint32_t u; asm("cvt.rna.tf32.f32 %0, %1;" : "=r"(u) : "f"(x));
    return __uint_as_float(u);
}
__device__ __forceinline__ uint32_t smem_u32(const void* p) {
    uint32_t a;
    asm("{ .reg .u64 t; cvta.to.shared.u64 t, %1; cvt.u32.u64 %0, t; }" : "=r"(a) : "l"(p));
    return a;
}
#define CP_ASYNC16(dst, src) \
    asm volatile("cp.async.cg.shared.global [%0], [%1], 16;" :: "r"(dst), "l"(src))
#define CP_COMMIT() asm volatile("cp.async.commit_group;" ::: "memory")
#define CP_WAIT(n)  asm volatile("cp.async.wait_group %0;" :: "n"(n) : "memory")

__device__ __forceinline__ void mma8(float* c, float4 a, float2 b) {
    asm volatile(
        "mma.sync.aligned.m16n8k8.row.col.f32.tf32.tf32.f32 "
        "{%0,%1,%2,%3}, {%4,%5,%6,%7}, {%8,%9}, {%0,%1,%2,%3};"
        : "+f"(c[0]), "+f"(c[1]), "+f"(c[2]), "+f"(c[3])
        : "r"(__float_as_uint(a.x)), "r"(__float_as_uint(a.y)),
          "r"(__float_as_uint(a.z)), "r"(__float_as_uint(a.w)),
          "r"(__float_as_uint(b.x)), "r"(__float_as_uint(b.y)));
}

// ---------------- init: zero all pads + c-states (1 launch) ----------------
__global__ void init_kernel() {
    long i = (long)blockIdx.x * 256 + threadIdx.x;
    long n;
    n = 3L * XC;      if (i < n) { g_padX[i] = 0.0f; return; }  i -= n;
    n = 2L * H1P;     if (i < n) { g_padH1[i] = 0.0f; return; } i -= n;
    n = 2L * L2P;     if (i < n) { g_padL2[i] = 0.0f; return; } i -= n;
    n = 2L * L2P;     if (i < n) { g_padL3[i] = 0.0f; return; } i -= n;
    n = BATCH * NF * NPIX;
    if (i < n) { g_c1[i] = 0.0f; return; } i -= n;
    if (i < n) { g_c2[i] = 0.0f; return; } i -= n;
    if (i < n) { g_c3[i] = 0.0f; return; }
}
#define INIT_TOTAL (3L*XC + 2L*H1P + 4L*L2P + 3L*BATCH*NF*NPIX)

// ---------------- weight prep: fragment-ordered gmem (1 launch) ----------------
// chunk = 32 k x 64 n' = 2048 floats: [ny8][ck][wn4][ks4][lane32][nf2][j2]
__device__ __forceinline__ void wstore(const float* __restrict__ W, float* __restrict__ out,
                                       int np, int k, int Cin, int NCH) {
    int K = Cin * 9;
    int ch = np >> 2, g = np & 3;
    int tap = k / Cin, ci = k - tap * Cin;
    float v = f2tf32(W[(size_t)(g * 128 + ch) * K + ci * 9 + tap]);
    int ny = np >> 6, n_t = np & 63;
    int wn = n_t >> 4, nl = n_t & 15;
    int nf = nl >> 3, rn = nl & 7;
    int ck = k >> 5, kl = k & 31, ks = kl >> 3, rk = kl & 7;
    int lane = rn * 4 + (rk & 3), j = rk >> 2;
    size_t off = (size_t)ny * NCH * 2048 + (size_t)ck * 2048 + wn * 512
               + ks * 128 + lane * 4 + nf * 2 + j;
    out[off] = v;
}
__global__ void wprep_kernel(const float* __restrict__ W1, const float* __restrict__ b1,
                             const float* __restrict__ W2, const float* __restrict__ b2,
                             const float* __restrict__ W3, const float* __restrict__ b3) {
    int idx = blockIdx.x * 256 + threadIdx.x;
    if (idx < 512) {
        int src = (idx & 3) * 128 + (idx >> 2);
        g_bp1[idx] = b1[src]; g_bp2[idx] = b2[src]; g_bp3[idx] = b3[src];
    }
    if (idx >= K1 * 512) return;
    int np = idx & 511, k = idx >> 9;
    wstore(W1, g_wf1, np, k, CIN1, NCH1);
    if (k < K23) {
        wstore(W2, g_wf2, np, k, CIN23, NCH23);
        wstore(W3, g_wf3, np, k, CIN23, NCH23);
    }
}

// ---------------- per-step x pack: 3 shifted copies (8 launches) ----------------
__global__ void pack_x_kernel(const float* __restrict__ x1, const float* __restrict__ x2, int t) {
    int idx = blockIdx.x * 256 + threadIdx.x;       // over BATCH*256*NPIX
    if (idx >= BATCH * 256 * NPIX) return;
    int pix = idx & 1023;
    int ci  = (idx >> 10) & 255;
    int b   = idx >> 18;
    float v = (ci < 128) ? x1[((b * TT + t) * NF + ci) * NPIX + pix]
                         : x2[((b * TT + t) * NF + (ci - 128)) * NPIX + pix];
    v = f2tf32(v);
    int plane = (b << 8) + ci;
    int py = (pix >> 5) + 1, px = (pix & 31) + 1;
    int base = (plane * 34 + py) * 36 + px;
#pragma unroll
    for (int c = 0; c < 3; ++c)
        if (px - c >= 0) g_padX[c * XC + base - c] = v;
}

// ---------------- fused GEMM + LSTM kernel ----------------
// grid (64, 8), 256 threads (8 warps, 2m x 4n). Z[m][n'] = sum_k A[m][k]*B[n'][k].
__global__ void __launch_bounds__(256, 3)
gemm_lstm_kernel(const float* __restrict__ Bf, const float* __restrict__ bp,
                 float* __restrict__ c_st, float* __restrict__ h_out,
                 int Cin, int NCH, int layer, int par)
{
    extern __shared__ float sm[];
    const uint32_t sb = smem_u32(sm);

    const int tid = threadIdx.x, w = tid >> 5, lane = tid & 31;
    const int wm = w >> 2, wn = w & 3, lane4 = lane & 3;
    const int m0 = blockIdx.x * BM, b = m0 >> 10, pix0 = m0 & 1023;
    const int ny = blockIdx.y;
    const float* Bny = Bf + (size_t)ny * NCH * 2048;

    // A loader coords: krow = tid>>4 and +16, m-float4 at m4 = (tid&15)*4
    const int kl16 = tid >> 4;
    const int m4   = (tid & 15) << 2;
    const int pixL = pix0 + m4;
    const int yL = pixL >> 5, xL = pixL & 31;

    float acc[2][2][4];
#pragma unroll
    for (int i = 0; i < 2; ++i)
#pragma unroll
        for (int jn = 0; jn < 2; ++jn)
#pragma unroll
            for (int q = 0; q < 4; ++q) acc[i][jn][q] = 0.0f;

    // ---- stage issue: 32-k chunk ----
    auto issue = [&](int ck, int s) {
        const uint32_t stA = sb + (s * STG) * 4;
        const uint32_t stB = stA + A_ST * 4;
#pragma unroll
        for (int jj = 0; jj < 2; ++jj) {
            const int krow = kl16 + (jj << 4);
            const int kg = (ck << 5) + krow;
            const int tap = kg / Cin;
            const int ci  = kg - tap * Cin;
            const int kh = tap / 3, kw = tap - kh * 3;
            const int row = yL + kh;
            const float* src;
            if (layer == 1) {
                if (ci < 256)
                    src = g_padX + (size_t)kw * XC + (((b << 8) + ci) * 34 + row) * 36 + xL;
                else
                    src = g_padH1 + (size_t)par * H1P + (size_t)kw * H1C
                        + (((b << 7) + ci - 256) * 34 + row) * 36 + xL;
            } else if (layer == 2) {
                src = g_padL2 + (size_t)par * L2P + (size_t)kw * L2C
                    + (((b << 8) + ci) * 34 + row) * 36 + xL;
            } else {
                src = g_padL3 + (size_t)par * L2P + (size_t)kw * L2C
                    + (((b << 8) + ci) * 34 + row) * 36 + xL;
            }
            CP_ASYNC16(stA + (krow * 72 + m4) * 4, src);
        }
        const float* bsrc = Bny + ((size_t)ck << 11) + (tid << 2);
#pragma unroll
        for (int q = 0; q < 2; ++q)
            CP_ASYNC16(stB + (((q << 8) + tid) << 4), bsrc + (q << 10));
        CP_COMMIT();
    };

    // ---- pipeline ----
#pragma unroll
    for (int s = 0; s < STAGES - 1; ++s) issue(s, s);

    for (int ck = 0; ck < NCH; ++ck) {
        CP_WAIT(STAGES - 2);
        __syncthreads();
        const int nx = ck + STAGES - 1;
        if (nx < NCH) issue(nx, nx & (STAGES - 1));

        const float* As = sm + (ck & (STAGES - 1)) * STG;
        const float* Bs = As + A_ST + (wn << 9);
#pragma unroll
        for (int ks = 0; ks < 4; ++ks) {
            const int kq = (ks << 3) + lane4;
            float4 af[2];
#pragma unroll
            for (int mf = 0; mf < 2; ++mf) {
                const int mrow = (wm << 5) + (mf << 4) + (lane >> 2);
                af[mf].x = As[kq * 72 + mrow];
                af[mf].y = As[kq * 72 + mrow + 8];
                af[mf].z = As[(kq + 4) * 72 + mrow];
                af[mf].w = As[(kq + 4) * 72 + mrow + 8];
            }
            const float4 bv = *(const float4*)(Bs + (ks << 7) + (lane << 2));
            const float2 b0 = make_float2(bv.x, bv.y);
            const float2 b1 = make_float2(bv.z, bv.w);
            mma8(acc[0][0], af[0], b0);
            mma8(acc[0][1], af[0], b1);
            mma8(acc[1][0], af[1], b0);
            mma8(acc[1][1], af[1], b1);
        }
    }

    // ---- fused LSTM epilogue + pad writes for downstream consumers ----
#pragma unroll
    for (int nf = 0; nf < 2; ++nf) {
        const int nc = (ny << 6) + (wn << 4) + (nf << 3) + (lane4 << 1);
        const float bb0 = __ldg(bp + nc),     bb1 = __ldg(bp + nc + 1);
        const float bb2 = __ldg(bp + nc + 2), bb3 = __ldg(bp + nc + 3);
        const int ch = nc >> 2;
#pragma unroll
        for (int mf = 0; mf < 2; ++mf) {
#pragma unroll
            for (int rh = 0; rh < 2; ++rh) {
                float v0 = acc[mf][nf][rh * 2 + 0];
                float v1 = acc[mf][nf][rh * 2 + 1];
                float p0 = __shfl_xor_sync(0xffffffffu, v0, 1);
                float p1 = __shfl_xor_sync(0xffffffffu, v1, 1);
                if (!(lane & 1)) {
                    const float zi = v0 + bb0, zf = v1 + bb1, zo = p0 + bb2, zg = p1 + bb3;
                    const float gi = 1.0f / (1.0f + expf(-zi));
                    const float gf = 1.0f / (1.0f + expf(-zf));
                    const float go = 1.0f / (1.0f + expf(-zo));
                    const float gg = tanhf(zg);
                    const int pixm = pix0 + (wm << 5) + (mf << 4) + (lane >> 2) + (rh << 3);
                    const int sidx = ((((b << 7) + ch)) << 10) + pixm;
                    const float cn = gf * c_st[sidx] + gi * gg;
                    c_st[sidx] = cn;
                    const float hn = go * tanhf(cn);
                    const float hr = f2tf32(hn);
                    const int py = (pixm >> 5) + 1, px = (pixm & 31) + 1;
                    if (layer == 1) {
                        const int o1 = ((b << 7) + ch) * 34 + py;
                        const int o2 = ((b << 8) + ch) * 34 + py;
                        const size_t p1b = (size_t)(par ^ 1) * H1P;
                        const size_t p2b = (size_t)par * L2P;
#pragma unroll
                        for (int c = 0; c < 3; ++c) if (px - c >= 0) {
                            g_padH1[p1b + (size_t)c * H1C + o1 * 36 + px - c] = hr;
                            g_padL2[p2b + (size_t)c * L2C + o2 * 36 + px - c] = hr;
                        }
                    } else if (layer == 2) {
                        const int o2 = ((b << 8) + 128 + ch) * 34 + py;
                        const int o3 = ((b << 8) + ch) * 34 + py;
                        const size_t p2b = (size_t)(par ^ 1) * L2P;
                        const size_t p3b = (size_t)par * L2P;
#pragma unroll
                        for (int c = 0; c < 3; ++c) if (px - c >= 0) {
                            g_padL2[p2b + (size_t)c * L2C + o2 * 36 + px - c] = hr;
                            g_padL3[p3b + (size_t)c * L2C + o3 * 36 + px - c] = hr;
                        }
                    } else {
                        const int o3 = ((b << 8) + 128 + ch) * 34 + py;
                        const size_t p3b = (size_t)(par ^ 1) * L2P;
#pragma unroll
                        for (int c = 0; c < 3; ++c) if (px - c >= 0)
                            g_padL3[p3b + (size_t)c * L2C + o3 * 36 + px - c] = hr;
                        h_out[sidx] = hn;
                    }
                }
            }
        }
    }
}

// ---------------- launch ----------------
extern "C" void kernel_launch(void* const* d_in, const int* in_sizes, int n_in,
                              void* d_out, int out_size) {
    const float* x1 = (const float*)d_in[0];
    const float* x2 = (const float*)d_in[1];
    const float* W1 = (const float*)d_in[2];
    const float* b1 = (const float*)d_in[3];
    const float* W2 = (const float*)d_in[4];
    const float* b2 = (const float*)d_in[5];
    const float* W3 = (const float*)d_in[6];
    const float* b3 = (const float*)d_in[7];
    float* out = (float*)d_out;

    float *p_c1, *p_c2, *p_c3, *p_wf1, *p_wf2, *p_wf3, *p_bp1, *p_bp2, *p_bp3;
    cudaGetSymbolAddress((void**)&p_c1, g_c1);
    cudaGetSymbolAddress((void**)&p_c2, g_c2);
    cudaGetSymbolAddress((void**)&p_c3, g_c3);
    cudaGetSymbolAddress((void**)&p_wf1, g_wf1);
    cudaGetSymbolAddress((void**)&p_wf2, g_wf2);
    cudaGetSymbolAddress((void**)&p_wf3, g_wf3);
    cudaGetSymbolAddress((void**)&p_bp1, g_bp1);
    cudaGetSymbolAddress((void**)&p_bp2, g_bp2);
    cudaGetSymbolAddress((void**)&p_bp3, g_bp3);

    cudaFuncSetAttribute(gemm_lstm_kernel,
                         cudaFuncAttributeMaxDynamicSharedMemorySize, SMEM_DYN);

    const dim3 ggrid(64, 8);
    const int initBlocks = (int)((INIT_TOTAL + 255) / 256);

    init_kernel<<<initBlocks, 256>>>();
    wprep_kernel<<<(K1 * 512 + 255) / 256, 256>>>(W1, b1, W2, b2, W3, b3);

    for (int t = 0; t < TT; ++t) {
        const int par = t & 1;
        pack_x_kernel<<<(BATCH * 256 * NPIX + 255) / 256, 256>>>(x1, x2, t);
        gemm_lstm_kernel<<<ggrid, 256, SMEM_DYN>>>(p_wf1, p_bp1, p_c1, nullptr,
                                                   CIN1, NCH1, 1, par);
        gemm_lstm_kernel<<<ggrid, 256, SMEM_DYN>>>(p_wf2, p_bp2, p_c2, nullptr,
                                                   CIN23, NCH23, 2, par);
        gemm_lstm_kernel<<<ggrid, 256, SMEM_DYN>>>(p_wf3, p_bp3, p_c3, out,
                                                   CIN23, NCH23, 3, par);
    }
}

// round 10
// speedup vs baseline: 1.1820x; 1.1820x over previous
#include <cuda_runtime.h>
#include <cstdint>
#include <math.h>

// ---------------- problem constants ----------------
#define NF     128
#define BATCH  4
#define TT     8
#define NPIX   1024
#define CIN1   384
#define CIN23  256
#define K1     (CIN1 * 9)     // 3456
#define PADPL  (34 * 36)

// pad buffer strides (floats)
#define XC   (BATCH * 256 * PADPL)
#define H1C  (BATCH * 128 * PADPL)
#define H1P  (3 * H1C)
#define L2C  (BATCH * 256 * PADPL)
#define L2P  (3 * L2C)

// GEMM tiling: CTA 64x128x32, 16 warps (4m x 4n), warp tile 16x32, mma m16n8k8
#define BM 64
#define STAGES 4
#define A_ST 2304              // 32 k-rows * 72 (72 mod 32 == 8: bank-bijective)
#define B_ST 4096              // 128 n * 32 k
#define STG  (A_ST + B_ST)     // 6400 floats per stage
#define SMEM_DYN (STAGES * STG * 4)   // 102400 B -> 2 CTAs/SM

// ---------------- persistent device scratch ----------------
__device__ __align__(256) float g_padX[3 * XC];
__device__ __align__(256) float g_padH1[2 * H1P];
__device__ __align__(256) float g_padL2[2 * L2P];
__device__ __align__(256) float g_padL3[2 * L2P];
__device__ __align__(256) float g_c1[BATCH * NF * NPIX];
__device__ __align__(256) float g_c2[BATCH * NF * NPIX];
__device__ __align__(256) float g_c3[BATCH * NF * NPIX];
__device__ __align__(256) float g_wf1[K1 * 512];
__device__ __align__(256) float g_wf2[CIN23 * 9 * 512];
__device__ __align__(256) float g_wf3[CIN23 * 9 * 512];
__device__ float g_bp1[512];
__device__ float g_bp2[512];
__device__ float g_bp3[512];

__device__ __forceinline__ float f2tf32(float x) {
    uint32_t u; asm("cvt.rna.tf32.f32 %0, %1;" : "=r"(u) : "f"(x));
    return __uint_as_float(u);
}
__device__ __forceinline__ uint32_t smem_u32(const void* p) {
    uint32_t a;
    asm("{ .reg .u64 t; cvta.to.shared.u64 t, %1; cvt.u32.u64 %0, t; }" : "=r"(a) : "l"(p));
    return a;
}
#define CP_ASYNC16(dst, src) \
    asm volatile("cp.async.cg.shared.global [%0], [%1], 16;" :: "r"(dst), "l"(src))
#define CP_COMMIT() asm volatile("cp.async.commit_group;" ::: "memory")
#define CP_WAIT(n)  asm volatile("cp.async.wait_group %0;" :: "n"(n) : "memory")

__device__ __forceinline__ void mma8(float* c, float4 a, float2 b) {
    asm volatile(
        "mma.sync.aligned.m16n8k8.row.col.f32.tf32.tf32.f32 "
        "{%0,%1,%2,%3}, {%4,%5,%6,%7}, {%8,%9}, {%0,%1,%2,%3};"
        : "+f"(c[0]), "+f"(c[1]), "+f"(c[2]), "+f"(c[3])
        : "r"(__float_as_uint(a.x)), "r"(__float_as_uint(a.y)),
          "r"(__float_as_uint(a.z)), "r"(__float_as_uint(a.w)),
          "r"(__float_as_uint(b.x)), "r"(__float_as_uint(b.y)));
}

// ---------------- init: zero all pads + c-states (1 launch) ----------------
__global__ void init_kernel() {
    long i = (long)blockIdx.x * 256 + threadIdx.x;
    long n;
    n = 3L * XC;      if (i < n) { g_padX[i] = 0.0f; return; }  i -= n;
    n = 2L * H1P;     if (i < n) { g_padH1[i] = 0.0f; return; } i -= n;
    n = 2L * L2P;     if (i < n) { g_padL2[i] = 0.0f; return; } i -= n;
    n = 2L * L2P;     if (i < n) { g_padL3[i] = 0.0f; return; } i -= n;
    n = BATCH * NF * NPIX;
    if (i < n) { g_c1[i] = 0.0f; return; } i -= n;
    if (i < n) { g_c2[i] = 0.0f; return; } i -= n;
    if (i < n) { g_c3[i] = 0.0f; return; }
}
#define INIT_TOTAL (3L*XC + 2L*H1P + 4L*L2P + 3L*BATCH*NF*NPIX)

// ---------------- weight prep: fragment-ordered gmem (1 launch) ----------------
// chunk = 32 k x 128 n' = 4096 floats: [ny4][ck][wn4][ks4][nf2 2][lane32][f2][j2]
__device__ __forceinline__ void wstore(const float* __restrict__ W, float* __restrict__ out,
                                       int np, int k, int Cin, int NCH) {
    int K = Cin * 9;
    int ch = np >> 2, g = np & 3;
    int tap = k / Cin, ci = k - tap * Cin;
    float v = f2tf32(W[(size_t)(g * 128 + ch) * K + ci * 9 + tap]);
    int ny = np >> 7, n_t = np & 127;
    int wn = n_t >> 5, nl = n_t & 31;
    int nf = nl >> 3, rn = nl & 7, nf2 = nf >> 1, f = nf & 1;
    int ck = k >> 5, kl = k & 31, ks = kl >> 3, rk = kl & 7;
    int lane = rn * 4 + (rk & 3), j = rk >> 2;
    size_t off = (size_t)ny * NCH * 4096 + (size_t)ck * 4096 + wn * 1024
               + ks * 256 + nf2 * 128 + lane * 4 + f * 2 + j;
    out[off] = v;
}
__global__ void wprep_kernel(const float* __restrict__ W1, const float* __restrict__ b1,
                             const float* __restrict__ W2, const float* __restrict__ b2,
                             const float* __restrict__ W3, const float* __restrict__ b3) {
    int idx = blockIdx.x * 256 + threadIdx.x;
    if (idx < 512) {
        int src = (idx & 3) * 128 + (idx >> 2);
        g_bp1[idx] = b1[src]; g_bp2[idx] = b2[src]; g_bp3[idx] = b3[src];
    }
    if (idx >= K1 * 512) return;
    int np = idx & 511, k = idx >> 9;
    wstore(W1, g_wf1, np, k, CIN1, CIN1 * 9 / 32);
    if (k < CIN23 * 9) {
        wstore(W2, g_wf2, np, k, CIN23, CIN23 * 9 / 32);
        wstore(W3, g_wf3, np, k, CIN23, CIN23 * 9 / 32);
    }
}

// ---------------- per-step x pack: 3 shifted copies (8 launches) ----------------
__global__ void pack_x_kernel(const float* __restrict__ x1, const float* __restrict__ x2, int t) {
    int idx = blockIdx.x * 256 + threadIdx.x;
    if (idx >= BATCH * 256 * NPIX) return;
    int pix = idx & 1023;
    int ci  = (idx >> 10) & 255;
    int b   = idx >> 18;
    float v = (ci < 128) ? x1[((b * TT + t) * NF + ci) * NPIX + pix]
                         : x2[((b * TT + t) * NF + (ci - 128)) * NPIX + pix];
    v = f2tf32(v);
    int plane = (b << 8) + ci;
    int py = (pix >> 5) + 1, px = (pix & 31) + 1;
    int base = (plane * 34 + py) * 36 + px;
#pragma unroll
    for (int c = 0; c < 3; ++c)
        if (px - c >= 0) g_padX[c * XC + base - c] = v;
}

// ---------------- fused GEMM + LSTM kernel ----------------
// grid (64, 4), 512 threads (16 warps, 4m x 4n, warp tile 16x32).
template <int CIN, int LAYER>
__global__ void __launch_bounds__(512, 2)
gemm_lstm_kernel(const float* __restrict__ Bf, const float* __restrict__ bp,
                 float* __restrict__ c_st, float* __restrict__ h_out, int par)
{
    constexpr int NCH = CIN * 9 / 32;
    extern __shared__ float sm[];
    const uint32_t sb = smem_u32(sm);

    const int tid = threadIdx.x, w = tid >> 5, lane = tid & 31;
    const int wm = w >> 2, wn = w & 3, lane4 = lane & 3;
    const int m0 = blockIdx.x * BM, b = m0 >> 10, pix0 = m0 & 1023;
    const int ny = blockIdx.y;
    const float* Bny = Bf + (size_t)ny * NCH * 4096;

    // A loader: 512 threads cover 32 k-rows x 16 m-float4 exactly
    const int krowL = tid >> 4;          // 0..31
    const int m4    = (tid & 15) << 2;
    const int pixL  = pix0 + m4;
    const int yL = pixL >> 5, xL = pixL & 31;

    float acc[4][4];
#pragma unroll
    for (int jn = 0; jn < 4; ++jn)
#pragma unroll
        for (int q = 0; q < 4; ++q) acc[jn][q] = 0.0f;

    // ---- stage issue: 32-k chunk, 1 A + 2 B cp.async per thread ----
    auto issue = [&](int ck, int s) {
        const uint32_t stA = sb + (s * STG) * 4;
        const uint32_t stB = stA + A_ST * 4;
        {
            const int kg = (ck << 5) + krowL;
            const int tap = kg / CIN;            // compile-time divisor
            const int ci  = kg - tap * CIN;
            const int kh = tap / 3, kw = tap - kh * 3;
            const int row = yL + kh;
            const float* src;
            if (LAYER == 1) {
                if (ci < 256)
                    src = g_padX + (size_t)kw * XC + (((b << 8) + ci) * 34 + row) * 36 + xL;
                else
                    src = g_padH1 + (size_t)par * H1P + (size_t)kw * H1C
                        + (((b << 7) + ci - 256) * 34 + row) * 36 + xL;
            } else if (LAYER == 2) {
                src = g_padL2 + (size_t)par * L2P + (size_t)kw * L2C
                    + (((b << 8) + ci) * 34 + row) * 36 + xL;
            } else {
                src = g_padL3 + (size_t)par * L2P + (size_t)kw * L2C
                    + (((b << 8) + ci) * 34 + row) * 36 + xL;
            }
            CP_ASYNC16(stA + (krowL * 72 + m4) * 4, src);
        }
        const float* bsrc = Bny + ((size_t)ck << 12) + (tid << 2);
#pragma unroll
        for (int q = 0; q < 2; ++q)
            CP_ASYNC16(stB + (((q << 9) + tid) << 4), bsrc + (q << 11));
        CP_COMMIT();
    };

    // ---- pipeline ----
#pragma unroll
    for (int s = 0; s < STAGES - 1; ++s) issue(s, s);

    for (int ck = 0; ck < NCH; ++ck) {
        CP_WAIT(STAGES - 2);
        __syncthreads();
        const int nx = ck + STAGES - 1;
        if (nx < NCH) issue(nx, nx & (STAGES - 1));

        const float* As = sm + (ck & (STAGES - 1)) * STG;
        const float* Bs = As + A_ST + (wn << 10);
#pragma unroll
        for (int ks = 0; ks < 4; ++ks) {
            const int kq = (ks << 3) + lane4;
            const int mrow = (wm << 4) + (lane >> 2);
            float4 af;
            af.x = As[kq * 72 + mrow];
            af.y = As[kq * 72 + mrow + 8];
            af.z = As[(kq + 4) * 72 + mrow];
            af.w = As[(kq + 4) * 72 + mrow + 8];
#pragma unroll
            for (int nf2 = 0; nf2 < 2; ++nf2) {
                const float4 bv = *(const float4*)(Bs + (ks << 8) + (nf2 << 7) + (lane << 2));
                const float2 b0 = make_float2(bv.x, bv.y);
                const float2 b1 = make_float2(bv.z, bv.w);
                mma8(acc[nf2 * 2 + 0], af, b0);
                mma8(acc[nf2 * 2 + 1], af, b1);
            }
        }
    }

    // ---- fused LSTM epilogue + pad writes for downstream consumers ----
#pragma unroll
    for (int jn = 0; jn < 4; ++jn) {
        const int nc = (ny << 7) + (wn << 5) + (jn << 3) + (lane4 << 1);
        const float bb0 = __ldg(bp + nc),     bb1 = __ldg(bp + nc + 1);
        const float bb2 = __ldg(bp + nc + 2), bb3 = __ldg(bp + nc + 3);
        const int ch = nc >> 2;
#pragma unroll
        for (int rh = 0; rh < 2; ++rh) {
            float v0 = acc[jn][rh * 2 + 0];
            float v1 = acc[jn][rh * 2 + 1];
            float p0 = __shfl_xor_sync(0xffffffffu, v0, 1);
            float p1 = __shfl_xor_sync(0xffffffffu, v1, 1);
            if (!(lane & 1)) {
                const float zi = v0 + bb0, zf = v1 + bb1, zo = p0 + bb2, zg = p1 + bb3;
                const float gi = 1.0f / (1.0f + expf(-zi));
                const float gf = 1.0f / (1.0f + expf(-zf));
                const float go = 1.0f / (1.0f + expf(-zo));
                const float gg = tanhf(zg);
                const int pixm = pix0 + (wm << 4) + (lane >> 2) + (rh << 3);
                const int sidx = ((((b << 7) + ch)) << 10) + pixm;
                const float cn = gf * c_st[sidx] + gi * gg;
                c_st[sidx] = cn;
                const float hn = go * tanhf(cn);
                const float hr = f2tf32(hn);
                const int py = (pixm >> 5) + 1, px = (pixm & 31) + 1;
                if (LAYER == 1) {
                    const int o1 = ((b << 7) + ch) * 34 + py;
                    const int o2 = ((b << 8) + ch) * 34 + py;
                    const size_t p1b = (size_t)(par ^ 1) * H1P;
                    const size_t p2b = (size_t)par * L2P;
#pragma unroll
                    for (int c = 0; c < 3; ++c) if (px - c >= 0) {
                        g_padH1[p1b + (size_t)c * H1C + o1 * 36 + px - c] = hr;
                        g_padL2[p2b + (size_t)c * L2C + o2 * 36 + px - c] = hr;
                    }
                } else if (LAYER == 2) {
                    const int o2 = ((b << 8) + 128 + ch) * 34 + py;
                    const int o3 = ((b << 8) + ch) * 34 + py;
                    const size_t p2b = (size_t)(par ^ 1) * L2P;
                    const size_t p3b = (size_t)par * L2P;
#pragma unroll
                    for (int c = 0; c < 3; ++c) if (px - c >= 0) {
                        g_padL2[p2b + (size_t)c * L2C + o2 * 36 + px - c] = hr;
                        g_padL3[p3b + (size_t)c * L2C + o3 * 36 + px - c] = hr;
                    }
                } else {
                    const int o3 = ((b << 8) + 128 + ch) * 34 + py;
                    const size_t p3b = (size_t)(par ^ 1) * L2P;
#pragma unroll
                    for (int c = 0; c < 3; ++c) if (px - c >= 0)
                        g_padL3[p3b + (size_t)c * L2C + o3 * 36 + px - c] = hr;
                    h_out[sidx] = hn;
                }
            }
        }
    }
}

// ---------------- launch ----------------
extern "C" void kernel_launch(void* const* d_in, const int* in_sizes, int n_in,
                              void* d_out, int out_size) {
    const float* x1 = (const float*)d_in[0];
    const float* x2 = (const float*)d_in[1];
    const float* W1 = (const float*)d_in[2];
    const float* b1 = (const float*)d_in[3];
    const float* W2 = (const float*)d_in[4];
    const float* b2 = (const float*)d_in[5];
    const float* W3 = (const float*)d_in[6];
    const float* b3 = (const float*)d_in[7];
    float* out = (float*)d_out;

    float *p_c1, *p_c2, *p_c3, *p_wf1, *p_wf2, *p_wf3, *p_bp1, *p_bp2, *p_bp3;
    cudaGetSymbolAddress((void**)&p_c1, g_c1);
    cudaGetSymbolAddress((void**)&p_c2, g_c2);
    cudaGetSymbolAddress((void**)&p_c3, g_c3);
    cudaGetSymbolAddress((void**)&p_wf1, g_wf1);
    cudaGetSymbolAddress((void**)&p_wf2, g_wf2);
    cudaGetSymbolAddress((void**)&p_wf3, g_wf3);
    cudaGetSymbolAddress((void**)&p_bp1, g_bp1);
    cudaGetSymbolAddress((void**)&p_bp2, g_bp2);
    cudaGetSymbolAddress((void**)&p_bp3, g_bp3);

    cudaFuncSetAttribute(gemm_lstm_kernel<CIN1, 1>,
                         cudaFuncAttributeMaxDynamicSharedMemorySize, SMEM_DYN);
    cudaFuncSetAttribute(gemm_lstm_kernel<CIN23, 2>,
                         cudaFuncAttributeMaxDynamicSharedMemorySize, SMEM_DYN);
    cudaFuncSetAttribute(gemm_lstm_kernel<CIN23, 3>,
                         cudaFuncAttributeMaxDynamicSharedMemorySize, SMEM_DYN);

    const dim3 ggrid(64, 4);
    const int initBlocks = (int)((INIT_TOTAL + 255) / 256);

    init_kernel<<<initBlocks, 256>>>();
    wprep_kernel<<<(K1 * 512 + 255) / 256, 256>>>(W1, b1, W2, b2, W3, b3);

    for (int t = 0; t < TT; ++t) {
        const int par = t & 1;
        pack_x_kernel<<<(BATCH * 256 * NPIX + 255) / 256, 256>>>(x1, x2, t);
        gemm_lstm_kernel<CIN1, 1><<<ggrid, 512, SMEM_DYN>>>(p_wf1, p_bp1, p_c1, nullptr, par);
        gemm_lstm_kernel<CIN23, 2><<<ggrid, 512, SMEM_DYN>>>(p_wf2, p_bp2, p_c2, nullptr, par);
        gemm_lstm_kernel<CIN23, 3><<<ggrid, 512, SMEM_DYN>>>(p_wf3, p_bp3, p_c3, out, par);
    }
}

// round 11
// speedup vs baseline: 3.0062x; 2.5434x over previous
#include <cuda_runtime.h>
#include <cuda_fp16.h>
#include <cstdint>
#include <math.h>

// ---------------- problem constants ----------------
#define NF     128
#define BATCH  4
#define TT     8
#define NPIX   1024
#define C1     384
#define C23    256
#define K1     (C1 * 9)       // 3456
#define PADPL  (34 * 34)      // 1156 pixels, channel-last

// pad sizes (halves)
#define P1P (BATCH * PADPL * C1)    // 1,775,616
#define P2P (BATCH * PADPL * C23)   // 1,183,744

// GEMM tiling: CTA 64x128x32, 8 warps (2m x 4n), warp tile 32x32, mma m16n8k16
#define BM 64
#define STAGES 5
#define A_BYTES (64 * 40 * 2)       // 5120  (64 m-rows, stride 40 halves: conflict-free)
#define B_BYTES (4096 * 2)          // 8192  (128 n x 32 k halves)
#define STG_B  (A_BYTES + B_BYTES)  // 13312
#define SMEM_DYN (STAGES * STG_B)   // 66560 B

// ---------------- persistent device scratch ----------------
__device__ __align__(256) __half g_pad1[2 * P1P];   // [par][b][y][x][384]: x1|x2|h1
__device__ __align__(256) __half g_pad2[2 * P2P];   // [par][b][y][x][256]: h1|h2
__device__ __align__(256) __half g_pad3[2 * P2P];   // [par][b][y][x][256]: h2|h3
__device__ __align__(256) float g_c1[BATCH * NF * NPIX];
__device__ __align__(256) float g_c2[BATCH * NF * NPIX];
__device__ __align__(256) float g_c3[BATCH * NF * NPIX];
__device__ __align__(256) __half g_wf1[K1 * 512];
__device__ __align__(256) __half g_wf2[C23 * 9 * 512];
__device__ __align__(256) __half g_wf3[C23 * 9 * 512];
__device__ float g_bp1[512];
__device__ float g_bp2[512];
__device__ float g_bp3[512];

__device__ __forceinline__ uint32_t smem_u32(const void* p) {
    uint32_t a;
    asm("{ .reg .u64 t; cvta.to.shared.u64 t, %1; cvt.u32.u64 %0, t; }" : "=r"(a) : "l"(p));
    return a;
}
#define CP_ASYNC16(dst, src) \
    asm volatile("cp.async.cg.shared.global [%0], [%1], 16;" :: "r"(dst), "l"(src))
#define CP_COMMIT() asm volatile("cp.async.commit_group;" ::: "memory")
#define CP_WAIT(n)  asm volatile("cp.async.wait_group %0;" :: "n"(n) : "memory")

__device__ __forceinline__ void ldmatrix4(uint32_t* a, uint32_t addr) {
    asm volatile("ldmatrix.sync.aligned.m8n8.x4.shared.b16 {%0,%1,%2,%3}, [%4];"
                 : "=r"(a[0]), "=r"(a[1]), "=r"(a[2]), "=r"(a[3]) : "r"(addr));
}
__device__ __forceinline__ void mma16(float* c, const uint32_t* a, uint32_t b0, uint32_t b1) {
    asm volatile(
        "mma.sync.aligned.m16n8k16.row.col.f32.f16.f16.f32 "
        "{%0,%1,%2,%3}, {%4,%5,%6,%7}, {%8,%9}, {%0,%1,%2,%3};"
        : "+f"(c[0]), "+f"(c[1]), "+f"(c[2]), "+f"(c[3])
        : "r"(a[0]), "r"(a[1]), "r"(a[2]), "r"(a[3]), "r"(b0), "r"(b1));
}

// ---------------- init: zero pads + c-states (1 launch) ----------------
__global__ void init_kernel() {
    long i = (long)blockIdx.x * 256 + threadIdx.x;
    long n;
    n = P1P;                 if (i < n) { ((uint32_t*)g_pad1)[i] = 0u; return; } i -= n;
    n = P2P;                 if (i < n) { ((uint32_t*)g_pad2)[i] = 0u; return; } i -= n;
    n = P2P;                 if (i < n) { ((uint32_t*)g_pad3)[i] = 0u; return; } i -= n;
    n = BATCH * NF * NPIX;
    if (i < n) { g_c1[i] = 0.0f; return; } i -= n;
    if (i < n) { g_c2[i] = 0.0f; return; } i -= n;
    if (i < n) { g_c3[i] = 0.0f; return; }
}
#define INIT_TOTAL ((long)P1P + 2L * P2P + 3L * BATCH * NF * NPIX)

// ---------------- weight prep: fp16 fragment-ordered gmem ----------------
// chunk = 32k x 128n' = 4096 halves: [ny4][ck][wn4][ks2][pair2][lane32][jj2][bsel2][h2]
__device__ __forceinline__ void wstore(const float* __restrict__ W, __half* __restrict__ out,
                                       int np, int k, int Cin, int NCH) {
    int K = Cin * 9;
    int ch = np >> 2, g = np & 3;
    int tap = k / Cin, ci = k - tap * Cin;
    __half v = __float2half_rn(W[(size_t)(g * 128 + ch) * K + ci * 9 + tap]);
    int ny = np >> 7, n_t = np & 127;
    int wn = n_t >> 5, nl = n_t & 31;
    int j = nl >> 3, rn = nl & 7, pair = j >> 1, jj = j & 1;
    int ck = k >> 5, kl = k & 31, ks = kl >> 4, rk = kl & 15;
    int bsel = rk >> 3, c = (rk & 7) >> 1, hh = rk & 1;
    int lane = rn * 4 + c;
    size_t off = (size_t)(ny * NCH + ck) * 4096 + wn * 1024 + ks * 512
               + pair * 256 + lane * 8 + jj * 4 + bsel * 2 + hh;
    out[off] = v;
}
__global__ void wprep_kernel(const float* __restrict__ W1, const float* __restrict__ b1,
                             const float* __restrict__ W2, const float* __restrict__ b2,
                             const float* __restrict__ W3, const float* __restrict__ b3) {
    int idx = blockIdx.x * 256 + threadIdx.x;
    if (idx < 512) {
        int src = (idx & 3) * 128 + (idx >> 2);
        g_bp1[idx] = b1[src]; g_bp2[idx] = b2[src]; g_bp3[idx] = b3[src];
    }
    if (idx >= K1 * 512) return;
    int np = idx & 511, k = idx >> 9;
    wstore(W1, g_wf1, np, k, C1, K1 / 32);
    if (k < C23 * 9) {
        wstore(W2, g_wf2, np, k, C23, C23 * 9 / 32);
        wstore(W3, g_wf3, np, k, C23, C23 * 9 / 32);
    }
}

// ---------------- per-step x pack: channel-last transpose (8 launches) ------
// 128 blocks x 256 thr; warp handles one 32ch x 32pix tile via smem transpose.
__global__ void pack_x_kernel(const float* __restrict__ x1, const float* __restrict__ x2,
                              int t, int par) {
    __shared__ __half tile[8][32][33];
    const int w = threadIdx.x >> 5, lane = threadIdx.x & 31;
    const int tl = blockIdx.x * 8 + w;          // 0..1023
    const int b = tl >> 8, rest = tl & 255;
    const int cb = rest >> 5, pb = rest & 31;
    const int ch0 = cb * 32, pix0 = pb * 32;

    const float* src = (ch0 < 128) ? (x1 + ((size_t)(b * TT + t) * 128 + ch0) * NPIX)
                                   : (x2 + ((size_t)(b * TT + t) * 128 + ch0 - 128) * NPIX);
#pragma unroll
    for (int r = 0; r < 32; ++r)
        tile[w][r][lane] = __float2half_rn(src[(size_t)r * NPIX + pix0 + lane]);
    __syncwarp();

    __half* dst0 = g_pad1 + (size_t)par * P1P;
#pragma unroll
    for (int p = 0; p < 32; p += 2) {
        const int pp = p + (lane >> 4), ll = lane & 15;
        const int pix = pix0 + pp;
        const int py = (pix >> 5) + 1, px = (pix & 31) + 1;
        uint32_t v = ((uint32_t)__half_as_ushort(tile[w][2 * ll + 1][pp]) << 16)
                   | (uint32_t)__half_as_ushort(tile[w][2 * ll][pp]);
        __half* d = dst0 + ((size_t)((b * 34 + py) * 34 + px)) * C1 + ch0 + 2 * ll;
        *(uint32_t*)d = v;
    }
}

// ---------------- fused fp16 GEMM + LSTM kernel ----------------
// grid (64, 4), 256 threads (8 warps, 2m x 4n, warp tile 32x32), mma m16n8k16.
template <int C, int LAYER>
__global__ void __launch_bounds__(256, 2)
gemm_lstm_kernel(const __half* __restrict__ Bf, const float* __restrict__ bp,
                 float* __restrict__ c_st, float* __restrict__ h_out, int par)
{
    constexpr int NCH = C * 9 / 32;
    extern __shared__ char sm[];
    const uint32_t sb = smem_u32(sm);

    const int tid = threadIdx.x, w = tid >> 5, lane = tid & 31;
    const int wm = w >> 2, wn = w & 3;
    const int m0 = blockIdx.x * BM, b = m0 >> 10, pix0 = m0 & 1023;
    const int ny = blockIdx.y;
    const __half* Bny = Bf + (size_t)ny * NCH * 4096;

    // A loader: thread -> pixel px (0..63), ch-quarter chq (0,8,16,24)
    const int px  = tid >> 2;
    const int chq = (tid & 3) << 3;
    const int pixL = pix0 + px;
    const int yL = pixL >> 5, xL = pixL & 31;

    const __half* padIn =
        (LAYER == 1) ? (g_pad1 + (size_t)par * P1P)
      : (LAYER == 2) ? (g_pad2 + (size_t)par * P2P)
                     : (g_pad3 + (size_t)par * P2P);

    // ldmatrix lane geometry
    const int q = lane >> 3, r = lane & 7;
    const int arow = (wm * 32 + (q & 1) * 8 + r) * 40 + (q >> 1) * 8;

    float acc[2][4][4];
#pragma unroll
    for (int mt = 0; mt < 2; ++mt)
#pragma unroll
        for (int jn = 0; jn < 4; ++jn)
#pragma unroll
            for (int qq = 0; qq < 4; ++qq) acc[mt][jn][qq] = 0.0f;

    auto issue = [&](int ck, int s) {
        const uint32_t stA = sb + s * STG_B;
        const uint32_t stB = stA + A_BYTES;
        const int kg = ck << 5;
        const int tap = kg / C;                 // compile-time divisor
        const int ch0 = kg - tap * C;
        const int kh = tap / 3, kw = tap - kh * 3;
        const __half* srcA = padIn
            + ((size_t)((b * 34 + yL + kh) * 34 + xL + kw)) * C + ch0 + chq;
        CP_ASYNC16(stA + (px * 40 + chq) * 2, srcA);
        const __half* srcB = Bny + ((size_t)ck << 12) + (tid << 3);
        CP_ASYNC16(stB + tid * 16, srcB);
        CP_ASYNC16(stB + 4096 + tid * 16, srcB + 2048);
        CP_COMMIT();
    };

#pragma unroll
    for (int s = 0; s < STAGES - 1; ++s) issue(s, s);

    int st = 0;
    for (int ck = 0; ck < NCH; ++ck) {
        CP_WAIT(STAGES - 2);
        __syncthreads();
        const int nx = ck + STAGES - 1;
        if (nx < NCH) {
            int sn = st + STAGES - 1; if (sn >= STAGES) sn -= STAGES;
            issue(nx, sn);
        }
        const uint32_t As = sb + st * STG_B;
        const uint32_t Bs = As + A_BYTES + (wn << 11);
#pragma unroll
        for (int ks = 0; ks < 2; ++ks) {
            uint32_t af[2][4];
#pragma unroll
            for (int mt = 0; mt < 2; ++mt)
                ldmatrix4(af[mt], As + (arow + mt * 640 + ks * 16) * 2);
#pragma unroll
            for (int pair = 0; pair < 2; ++pair) {
                const uint4 bv = *(const uint4*)(size_t)(0);
                (void)bv;
                uint4 bq;
                asm volatile("ld.shared.v4.b32 {%0,%1,%2,%3}, [%4];"
                             : "=r"(bq.x), "=r"(bq.y), "=r"(bq.z), "=r"(bq.w)
                             : "r"(Bs + (ks * 512 + pair * 256 + lane * 8) * 2));
#pragma unroll
                for (int mt = 0; mt < 2; ++mt) {
                    mma16(acc[mt][pair * 2 + 0], af[mt], bq.x, bq.y);
                    mma16(acc[mt][pair * 2 + 1], af[mt], bq.z, bq.w);
                }
            }
        }
        if (++st == STAGES) st = 0;
    }

    // ---- fused LSTM epilogue + channel-last pad writes ----
    const int lane4 = lane & 3;
#pragma unroll
    for (int mt = 0; mt < 2; ++mt) {
#pragma unroll
        for (int jn = 0; jn < 4; ++jn) {
            const int nc = (ny << 7) + (wn << 5) + (jn << 3) + (lane4 << 1);
            const float bb0 = __ldg(bp + nc),     bb1 = __ldg(bp + nc + 1);
            const float bb2 = __ldg(bp + nc + 2), bb3 = __ldg(bp + nc + 3);
            const int ch = nc >> 2;
#pragma unroll
            for (int rh = 0; rh < 2; ++rh) {
                float v0 = acc[mt][jn][rh * 2 + 0];
                float v1 = acc[mt][jn][rh * 2 + 1];
                float p0 = __shfl_xor_sync(0xffffffffu, v0, 1);
                float p1 = __shfl_xor_sync(0xffffffffu, v1, 1);
                if (!(lane & 1)) {
                    const float zi = v0 + bb0, zf = v1 + bb1, zo = p0 + bb2, zg = p1 + bb3;
                    const float gi = 1.0f / (1.0f + expf(-zi));
                    const float gf = 1.0f / (1.0f + expf(-zf));
                    const float go = 1.0f / (1.0f + expf(-zo));
                    const float gg = tanhf(zg);
                    const int pixm = pix0 + (wm << 5) + (mt << 4) + (lane >> 2) + (rh << 3);
                    const int sidx = (((b << 7) + ch) << 10) + pixm;
                    const float cn = gf * c_st[sidx] + gi * gg;
                    c_st[sidx] = cn;
                    const float hn = go * tanhf(cn);
                    const __half hr = __float2half_rn(hn);
                    const int py = (pixm >> 5) + 1, pxx = (pixm & 31) + 1;
                    const size_t ppos = (size_t)((b * 34 + py) * 34 + pxx);
                    if (LAYER == 1) {
                        g_pad1[(size_t)(par ^ 1) * P1P + ppos * C1 + 256 + ch] = hr;
                        g_pad2[(size_t)par * P2P + ppos * C23 + ch] = hr;
                    } else if (LAYER == 2) {
                        g_pad2[(size_t)(par ^ 1) * P2P + ppos * C23 + 128 + ch] = hr;
                        g_pad3[(size_t)par * P2P + ppos * C23 + ch] = hr;
                    } else {
                        g_pad3[(size_t)(par ^ 1) * P2P + ppos * C23 + 128 + ch] = hr;
                        h_out[sidx] = hn;
                    }
                }
            }
        }
    }
}

// ---------------- launch ----------------
extern "C" void kernel_launch(void* const* d_in, const int* in_sizes, int n_in,
                              void* d_out, int out_size) {
    const float* x1 = (const float*)d_in[0];
    const float* x2 = (const float*)d_in[1];
    const float* W1 = (const float*)d_in[2];
    const float* b1 = (const float*)d_in[3];
    const float* W2 = (const float*)d_in[4];
    const float* b2 = (const float*)d_in[5];
    const float* W3 = (const float*)d_in[6];
    const float* b3 = (const float*)d_in[7];
    float* out = (float*)d_out;

    float *p_c1, *p_c2, *p_c3, *p_bp1, *p_bp2, *p_bp3;
    __half *p_wf1, *p_wf2, *p_wf3;
    cudaGetSymbolAddress((void**)&p_c1, g_c1);
    cudaGetSymbolAddress((void**)&p_c2, g_c2);
    cudaGetSymbolAddress((void**)&p_c3, g_c3);
    cudaGetSymbolAddress((void**)&p_wf1, g_wf1);
    cudaGetSymbolAddress((void**)&p_wf2, g_wf2);
    cudaGetSymbolAddress((void**)&p_wf3, g_wf3);
    cudaGetSymbolAddress((void**)&p_bp1, g_bp1);
    cudaGetSymbolAddress((void**)&p_bp2, g_bp2);
    cudaGetSymbolAddress((void**)&p_bp3, g_bp3);

    cudaFuncSetAttribute(gemm_lstm_kernel<C1, 1>,
                         cudaFuncAttributeMaxDynamicSharedMemorySize, SMEM_DYN);
    cudaFuncSetAttribute(gemm_lstm_kernel<C23, 2>,
                         cudaFuncAttributeMaxDynamicSharedMemorySize, SMEM_DYN);
    cudaFuncSetAttribute(gemm_lstm_kernel<C23, 3>,
                         cudaFuncAttributeMaxDynamicSharedMemorySize, SMEM_DYN);

    const dim3 ggrid(64, 4);
    const int initBlocks = (int)((INIT_TOTAL + 255) / 256);

    init_kernel<<<initBlocks, 256>>>();
    wprep_kernel<<<(K1 * 512 + 255) / 256, 256>>>(W1, b1, W2, b2, W3, b3);

    for (int t = 0; t < TT; ++t) {
        const int par = t & 1;
        pack_x_kernel<<<128, 256>>>(x1, x2, t, par);
        gemm_lstm_kernel<C1, 1><<<ggrid, 256, SMEM_DYN>>>(p_wf1, p_bp1, p_c1, nullptr, par);
        gemm_lstm_kernel<C23, 2><<<ggrid, 256, SMEM_DYN>>>(p_wf2, p_bp2, p_c2, nullptr, par);
        gemm_lstm_kernel<C23, 3><<<ggrid, 256, SMEM_DYN>>>(p_wf3, p_bp3, p_c3, out, par);
    }
}